// round 4
// baseline (speedup 1.0000x reference)
#include <cuda_runtime.h>
#include <stdint.h>

#define BB    16
#define DD    512
#define NN    2048
#define NSAMP 15
#define TOPK  16

// Scratch (allocation-free rule: __device__ globals)
__device__ float g_logits[(size_t)BB * NN * NN];   // 256 MB
__device__ float g_colsum[BB * NN];
__device__ float g_topval[(size_t)BB * NN * TOPK];
__device__ int   g_topcol[(size_t)BB * NN * TOPK];

// FMA-only exp (avoids MUFU wall). Rel err ~3e-8 on the needed range (x <= 0).
__device__ __forceinline__ float fast_exp(float x) {
    float t = fmaxf(x * 1.4426950408889634f, -120.0f);  // log2(e)
    float r = rintf(t);
    float f = t - r;
    float p =            1.5403530e-4f;   // ln2^6/720
    p = fmaf(p, f, 1.3333558e-3f);        // ln2^5/120
    p = fmaf(p, f, 9.6181291e-3f);        // ln2^4/24
    p = fmaf(p, f, 5.5504109e-2f);        // ln2^3/6
    p = fmaf(p, f, 2.4022651e-1f);        // ln2^2/2
    p = fmaf(p, f, 6.9314718e-1f);        // ln2
    p = fmaf(p, f, 1.0f);
    return __int_as_float(__float_as_int(p) + ((int)r << 23));
}

__global__ void k_zero_colsum() {
    int i = blockIdx.x * 256 + threadIdx.x;
    if (i < BB * NN) g_colsum[i] = 0.0f;
}

// ---------------------------------------------------------------------------
// Kernel 1: logits[b, s, t] = (1/sqrt(512)) * sum_d A[b,d,s] * B[b,d,t]
// Classic 128x128 tile, K-step 16, 256 threads, 8x8 per thread. fp32.
// ---------------------------------------------------------------------------
__global__ __launch_bounds__(256) void k_gemm(const float* __restrict__ A0,
                                              const float* __restrict__ B0) {
    const int b = blockIdx.z;
    const float* A  = A0 + (size_t)b * DD * NN;   // A[d][s], row d contiguous in s
    const float* Bt = B0 + (size_t)b * DD * NN;   // B[d][t]
    float* C = g_logits + (size_t)b * NN * NN;
    const int m0 = blockIdx.y * 128;
    const int n0 = blockIdx.x * 128;

    __shared__ float As[16][128];
    __shared__ float Bs[16][128];

    float acc[8][8];
#pragma unroll
    for (int i = 0; i < 8; i++)
#pragma unroll
        for (int j = 0; j < 8; j++) acc[i][j] = 0.0f;

    const int tid = threadIdx.x;
    const int tx = tid & 15;    // 0..15 -> n sub
    const int ty = tid >> 4;    // 0..15 -> m sub

    for (int kt = 0; kt < DD; kt += 16) {
#pragma unroll
        for (int l = 0; l < 2; l++) {
            int f  = tid + l * 256;     // 0..511 float4 slots
            int k  = f >> 5;            // 0..15
            int c4 = f & 31;            // 0..31
            *(float4*)&As[k][c4 * 4] =
                *(const float4*)(A  + (size_t)(kt + k) * NN + m0 + c4 * 4);
            *(float4*)&Bs[k][c4 * 4] =
                *(const float4*)(Bt + (size_t)(kt + k) * NN + n0 + c4 * 4);
        }
        __syncthreads();
#pragma unroll
        for (int k = 0; k < 16; k++) {
            float ar[8], br[8];
#pragma unroll
            for (int i = 0; i < 8; i++) ar[i] = As[k][ty * 8 + i];
#pragma unroll
            for (int j = 0; j < 8; j++) br[j] = Bs[k][tx * 8 + j];
#pragma unroll
            for (int i = 0; i < 8; i++)
#pragma unroll
                for (int j = 0; j < 8; j++)
                    acc[i][j] = fmaf(ar[i], br[j], acc[i][j]);
        }
        __syncthreads();
    }

    const float scl = 0.04419417382415922f;  // 1/sqrt(512)
#pragma unroll
    for (int i = 0; i < 8; i++) {
        float* crow = C + (size_t)(m0 + ty * 8 + i) * NN + n0 + tx * 8;
        float4 v0 = make_float4(acc[i][0] * scl, acc[i][1] * scl,
                                acc[i][2] * scl, acc[i][3] * scl);
        float4 v1 = make_float4(acc[i][4] * scl, acc[i][5] * scl,
                                acc[i][6] * scl, acc[i][7] * scl);
        *(float4*)crow       = v0;
        *(float4*)(crow + 4) = v1;
    }
}

// ---------------------------------------------------------------------------
// Kernel 2: per row — softmax (max, sum, normalize), accumulate column sums,
// extract top-16 (score, col) with exact row-major tie semantics.
// Block = 32 rows of one batch, 256 threads (8 cols per thread per row).
// ---------------------------------------------------------------------------
__global__ __launch_bounds__(256) void k_softmax_top() {
    const int b    = blockIdx.y;
    const int row0 = blockIdx.x * 32;
    const int tid  = threadIdx.x;
    const int lane = tid & 31;
    const int wid  = tid >> 5;

    __shared__ float colAcc[NN];                 // 8 KB
    __shared__ float s_red[8];
    __shared__ unsigned long long s_k[8];

    for (int i = tid; i < NN; i += 256) colAcc[i] = 0.0f;
    __syncthreads();

    for (int r = 0; r < 32; r++) {
        const int row = row0 + r;
        const float* L = g_logits + ((size_t)b * NN + row) * NN;

        float v[8];
#pragma unroll
        for (int k = 0; k < 8; k++) v[k] = L[tid + k * 256];

        // row max
        float m = v[0];
#pragma unroll
        for (int k = 1; k < 8; k++) m = fmaxf(m, v[k]);
#pragma unroll
        for (int off = 16; off; off >>= 1)
            m = fmaxf(m, __shfl_xor_sync(0xFFFFFFFFu, m, off));
        if (lane == 0) s_red[wid] = m;
        __syncthreads();
        float bm = s_red[0];
#pragma unroll
        for (int w = 1; w < 8; w++) bm = fmaxf(bm, s_red[w]);
        __syncthreads();  // protect s_red before reuse

        // exp + sum
        float sum = 0.0f;
#pragma unroll
        for (int k = 0; k < 8; k++) { v[k] = fast_exp(v[k] - bm); sum += v[k]; }
#pragma unroll
        for (int off = 16; off; off >>= 1)
            sum += __shfl_xor_sync(0xFFFFFFFFu, sum, off);
        if (lane == 0) s_red[wid] = sum;
        __syncthreads();
        float Z = 0.0f;
#pragma unroll
        for (int w = 0; w < 8; w++) Z += s_red[w];
        float inv = 1.0f / Z;
#pragma unroll
        for (int k = 0; k < 8; k++) {
            v[k] *= inv;
            colAcc[tid + k * 256] += v[k];
        }

        // top-16 via 16 block-argmax rounds on key = (bits(score) << 32) | ~col
        // (scores > 0 so float bits order monotonically; tie -> smaller col)
        unsigned msk = 0;
        for (int it = 0; it < TOPK; it++) {
            unsigned long long best = 0ull;
#pragma unroll
            for (int k = 0; k < 8; k++) {
                if (msk & (1u << k)) continue;
                unsigned col = (unsigned)tid + (unsigned)k * 256u;
                unsigned long long key =
                    ((unsigned long long)__float_as_uint(v[k]) << 32) |
                    (unsigned long long)(0xFFFFFFFFu - col);
                if (key > best) best = key;
            }
#pragma unroll
            for (int off = 16; off; off >>= 1) {
                unsigned long long o = __shfl_xor_sync(0xFFFFFFFFu, best, off);
                if (o > best) best = o;
            }
            __syncthreads();   // protect s_k from previous round
            if (lane == 0) s_k[wid] = best;
            __syncthreads();
            unsigned long long g = s_k[0];
#pragma unroll
            for (int w = 1; w < 8; w++) if (s_k[w] > g) g = s_k[w];
            unsigned col = 0xFFFFFFFFu - (unsigned)(g & 0xFFFFFFFFu);
            if ((col & 255u) == (unsigned)tid) msk |= 1u << (col >> 8);
            if (tid == 0) {
                g_topval[((size_t)b * NN + row) * TOPK + it] =
                    __uint_as_float((unsigned)(g >> 32));
                g_topcol[((size_t)b * NN + row) * TOPK + it] = (int)col;
            }
        }
        __syncthreads();  // protect s_red for next row
    }

    for (int i = tid; i < NN; i += 256)
        atomicAdd(&g_colsum[b * NN + i], colAcc[i]);
}

// ---------------------------------------------------------------------------
// Kernel 3: per batch — greedy matching from top-16 lists, Kabsch SVD (fp64
// Jacobi), translation from column sums. One block per batch.
// ---------------------------------------------------------------------------
__global__ __launch_bounds__(256) void k_match_tail(const float* __restrict__ src,
                                                    const float* __restrict__ tgt,
                                                    float* __restrict__ out) {
    const int b   = blockIdx.x;
    const int tid = threadIdx.x;

    __shared__ float sred[256];
    __shared__ float sums[6];
    __shared__ unsigned char used_col[NN];
    __shared__ unsigned char used_row[NN];
    __shared__ unsigned long long skey[256];
    __shared__ int scol[256];
    __shared__ int selR[NSAMP], selC[NSAMP];

    // reductions: sum of src points, and tgt weighted by colsum
    float a[6] = {0, 0, 0, 0, 0, 0};
    for (int n = tid; n < NN; n += 256) {
        const float* sp = src + ((size_t)b * NN + n) * 3;
        a[0] += sp[0]; a[1] += sp[1]; a[2] += sp[2];
        float w = g_colsum[b * NN + n];
        const float* tp = tgt + ((size_t)b * NN + n) * 3;
        a[3] += tp[0] * w; a[4] += tp[1] * w; a[5] += tp[2] * w;
    }
    for (int q = 0; q < 6; q++) {
        sred[tid] = a[q];
        __syncthreads();
        for (int off = 128; off; off >>= 1) {
            if (tid < off) sred[tid] += sred[tid + off];
            __syncthreads();
        }
        if (tid == 0) sums[q] = sred[0];
        __syncthreads();
    }

    // greedy matching
    for (int i = tid; i < NN; i += 256) { used_col[i] = 0; used_row[i] = 0; }
    __syncthreads();

    for (int it = 0; it < NSAMP; it++) {
        unsigned long long bk = 0ull; int bc = -1;
        for (int r = tid; r < NN; r += 256) {
            if (used_row[r]) continue;
            const float* tv = &g_topval[((size_t)b * NN + r) * TOPK];
            const int*   tc = &g_topcol[((size_t)b * NN + r) * TOPK];
            for (int e = 0; e < TOPK; e++) {
                int c = tc[e];
                if (used_col[c]) continue;
                unsigned long long key =
                    ((unsigned long long)__float_as_uint(tv[e]) << 32) |
                    (unsigned long long)(unsigned)(NN - r);   // tie -> smaller row
                if (key > bk) { bk = key; bc = c; }
                break;   // first valid entry is this row's best
            }
        }
        skey[tid] = bk; scol[tid] = bc;
        __syncthreads();
        for (int off = 128; off; off >>= 1) {
            if (tid < off && skey[tid + off] > skey[tid]) {
                skey[tid] = skey[tid + off];
                scol[tid] = scol[tid + off];
            }
            __syncthreads();
        }
        if (tid == 0) {
            int r = NN - (int)(skey[0] & 0xFFFFFFFFu);
            selR[it] = r;
            selC[it] = scol[0];
            used_row[r] = 1;
            used_col[scol[0]] = 1;
        }
        __syncthreads();
    }

    if (tid != 0) return;

    // ---- Kabsch on the 15 matched pairs (fp64) ----
    double sp[NSAMP][3], tp[NSAMP][3];
    double ms[3] = {0, 0, 0}, mt[3] = {0, 0, 0};
    for (int s = 0; s < NSAMP; s++) {
        const float* ps = src + ((size_t)b * NN + selR[s]) * 3;
        const float* pt = tgt + ((size_t)b * NN + selC[s]) * 3;
        for (int i = 0; i < 3; i++) {
            sp[s][i] = (double)ps[i];  ms[i] += sp[s][i];
            tp[s][i] = (double)pt[i];  mt[i] += tp[s][i];
        }
    }
    for (int i = 0; i < 3; i++) { ms[i] /= NSAMP; mt[i] /= NSAMP; }

    double Hm[3][3] = {{0,0,0},{0,0,0},{0,0,0}};
    for (int s = 0; s < NSAMP; s++)
        for (int i = 0; i < 3; i++)
            for (int j = 0; j < 3; j++)
                Hm[i][j] += (sp[s][i] - ms[i]) * (tp[s][j] - mt[j]);

    // A = H^T H ; Jacobi eigendecomposition -> V, lambda
    double Aq[3][3];
    for (int i = 0; i < 3; i++)
        for (int j = 0; j < 3; j++) {
            double acc = 0;
            for (int k = 0; k < 3; k++) acc += Hm[k][i] * Hm[k][j];
            Aq[i][j] = acc;
        }
    double Vv[3][3] = {{1,0,0},{0,1,0},{0,0,1}};
    const int prs[3][2] = {{0,1},{0,2},{1,2}};
    for (int rot = 0; rot < 36; rot++) {
        int p = prs[rot % 3][0], q = prs[rot % 3][1];
        double apq = Aq[p][q];
        if (fabs(apq) < 1e-300) continue;
        double theta = (Aq[q][q] - Aq[p][p]) / (2.0 * apq);
        double tt = (theta >= 0 ? 1.0 : -1.0) /
                    (fabs(theta) + sqrt(theta * theta + 1.0));
        double c = 1.0 / sqrt(tt * tt + 1.0);
        double s = tt * c;
        for (int k = 0; k < 3; k++) {
            double akp = Aq[k][p], akq = Aq[k][q];
            Aq[k][p] = c * akp - s * akq;
            Aq[k][q] = s * akp + c * akq;
        }
        for (int k = 0; k < 3; k++) {
            double apk = Aq[p][k], aqk = Aq[q][k];
            Aq[p][k] = c * apk - s * aqk;
            Aq[q][k] = s * apk + c * aqk;
        }
        for (int k = 0; k < 3; k++) {
            double vkp = Vv[k][p], vkq = Vv[k][q];
            Vv[k][p] = c * vkp - s * vkq;
            Vv[k][q] = s * vkp + c * vkq;
        }
    }
    double lam[3] = {Aq[0][0], Aq[1][1], Aq[2][2]};
    int ord[3] = {0, 1, 2};
    for (int i = 0; i < 2; i++)
        for (int j = i + 1; j < 3; j++)
            if (lam[ord[j]] > lam[ord[i]]) { int t0 = ord[i]; ord[i] = ord[j]; ord[j] = t0; }

    double Vs[3][3], U[3][3];
    for (int i = 0; i < 3; i++) {
        double sg = sqrt(fmax(lam[ord[i]], 1e-300));
        for (int k = 0; k < 3; k++) Vs[k][i] = Vv[k][ord[i]];
        for (int k = 0; k < 3; k++) {
            double acc = 0;
            for (int j = 0; j < 3; j++) acc += Hm[k][j] * Vs[j][i];
            U[k][i] = acc / sg;
        }
    }
    double Rr[3][3];
    for (int i = 0; i < 3; i++)
        for (int j = 0; j < 3; j++) {
            double acc = 0;
            for (int k = 0; k < 3; k++) acc += Vs[i][k] * U[j][k];
            Rr[i][j] = acc;
        }
    double det = Rr[0][0] * (Rr[1][1] * Rr[2][2] - Rr[1][2] * Rr[2][1])
               - Rr[0][1] * (Rr[1][0] * Rr[2][2] - Rr[1][2] * Rr[2][0])
               + Rr[0][2] * (Rr[1][0] * Rr[2][1] - Rr[1][1] * Rr[2][0]);
    if (det < 0) {
        for (int k = 0; k < 3; k++) Vs[k][2] = -Vs[k][2];
        for (int i = 0; i < 3; i++)
            for (int j = 0; j < 3; j++) {
                double acc = 0;
                for (int k = 0; k < 3; k++) acc += Vs[i][k] * U[j][k];
                Rr[i][j] = acc;
            }
    }

    // t = -R @ mean(src) + (tgt @ colsum) / N
    double msrc[3] = {sums[0] / (double)NN, sums[1] / (double)NN, sums[2] / (double)NN};
    double corr[3] = {sums[3] / (double)NN, sums[4] / (double)NN, sums[5] / (double)NN};

    for (int i = 0; i < 3; i++)
        for (int j = 0; j < 3; j++)
            out[b * 9 + i * 3 + j] = (float)Rr[i][j];
    for (int i = 0; i < 3; i++) {
        double ti = -(Rr[i][0] * msrc[0] + Rr[i][1] * msrc[1] + Rr[i][2] * msrc[2]) + corr[i];
        out[BB * 9 + b * 3 + i] = (float)ti;
    }
}

// ---------------------------------------------------------------------------
extern "C" void kernel_launch(void* const* d_in, const int* in_sizes, int n_in,
                              void* d_out, int out_size) {
    const float* se  = (const float*)d_in[0];  // src_embedding [16,512,2048]
    const float* te  = (const float*)d_in[1];  // tgt_embedding [16,512,2048]
    const float* src = (const float*)d_in[2];  // src [16,2048,3]
    const float* tgt = (const float*)d_in[3];  // tgt [16,2048,3]
    float* out = (float*)d_out;

    k_zero_colsum<<<(BB * NN + 255) / 256, 256>>>();
    dim3 gg(NN / 128, NN / 128, BB);
    k_gemm<<<gg, 256>>>(se, te);
    k_softmax_top<<<dim3(NN / 32, BB), 256>>>();
    k_match_tail<<<BB, 256>>>(src, tgt, out);
}

// round 7
// speedup vs baseline: 1.1685x; 1.1685x over previous
#include <cuda_runtime.h>
#include <stdint.h>

#define BB    16
#define DD    512
#define NN    2048
#define NSAMP 15
#define TOPK  16
typedef unsigned long long u64;

// ---------------- scratch (__device__ globals; no allocation) ----------------
__device__ float g_logits[(size_t)BB * NN * NN];   // 256 MB
__device__ float g_colsum[BB * NN];
__device__ float g_topval[(size_t)BB * NN * TOPK];
__device__ int   g_topcol[(size_t)BB * NN * TOPK];

// ---------------- helpers ----------------
__device__ __forceinline__ uint32_t smem_u32(const void* p) {
    uint32_t a;
    asm("{ .reg .u64 t; cvta.to.shared.u64 t, %1; cvt.u32.u64 %0, t; }" : "=r"(a) : "l"(p));
    return a;
}
__device__ __forceinline__ void cp16(uint32_t dst, const void* src) {
    asm volatile("cp.async.cg.shared.global [%0], [%1], 16;" :: "r"(dst), "l"(src));
}
#define CP_COMMIT() asm volatile("cp.async.commit_group;" ::: "memory")

__device__ __forceinline__ void split_tf32(float x, uint32_t& hi, uint32_t& lo) {
    uint32_t h, l;
    asm("cvt.rna.tf32.f32 %0, %1;" : "=r"(h) : "f"(x));
    float r = x - __uint_as_float(h);
    asm("cvt.rna.tf32.f32 %0, %1;" : "=r"(l) : "f"(r));
    hi = h; lo = l;
}

#define MMA8(d, a, b)                                                              \
    asm volatile("mma.sync.aligned.m16n8k8.row.col.f32.tf32.tf32.f32 "             \
        "{%0,%1,%2,%3}, {%4,%5,%6,%7}, {%8,%9}, {%0,%1,%2,%3};"                    \
        : "+f"((d)[0]), "+f"((d)[1]), "+f"((d)[2]), "+f"((d)[3])                   \
        : "r"((a)[0]), "r"((a)[1]), "r"((a)[2]), "r"((a)[3]),                      \
          "r"((b)[0]), "r"((b)[1]))

__device__ __forceinline__ float fast_exp(float x) {
    float t = fmaxf(x * 1.4426950408889634f, -120.0f);
    float r = rintf(t);
    float f = t - r;
    float p = 1.5403530e-4f;
    p = fmaf(p, f, 1.3333558e-3f);
    p = fmaf(p, f, 9.6181291e-3f);
    p = fmaf(p, f, 5.5504109e-2f);
    p = fmaf(p, f, 2.4022651e-1f);
    p = fmaf(p, f, 6.9314718e-1f);
    p = fmaf(p, f, 1.0f);
    return __int_as_float(__float_as_int(p) + ((int)r << 23));
}

__global__ void k_zero_colsum() {
    int i = blockIdx.x * 256 + threadIdx.x;
    if (i < BB * NN) g_colsum[i] = 0.0f;
}

// ---------------------------------------------------------------------------
// GEMM via mma.sync tf32 (3xTF32 fp32 emulation).
// logits[b,s,t] = scl * sum_d A[b,d,s]*B[b,d,t].
// CTA: 128x128 tile, 256 threads (8 warps as 2(m) x 4(n) of 64x32 warp tiles).
// K-chunks of 32 (4 k8 steps), cp.async double buffer.
// Smem per stage: A[32][132] + B[32][132] fp32. 2 stages = 67584 B dynamic.
// ---------------------------------------------------------------------------
#define PADW 132
#define TILE_F (32 * PADW)          // floats per tile
#define STAGE_F (2 * TILE_F)        // A+B per stage

__global__ __launch_bounds__(256, 1) void k_gemm_mma(const float* __restrict__ A0,
                                                     const float* __restrict__ B0) {
    extern __shared__ float sm[];
    const int b = blockIdx.z;
    const int m0 = blockIdx.y * 128;
    const int n0 = blockIdx.x * 128;
    const float* A  = A0 + (size_t)b * DD * NN;
    const float* Bt = B0 + (size_t)b * DD * NN;

    const int tid = threadIdx.x;
    const int lane = tid & 31;
    const int wid = tid >> 5;
    const int wm = wid & 1;          // 0..1 -> m block of 64
    const int wn = wid >> 1;         // 0..3 -> n block of 32

    float acc[4][4][4];
#pragma unroll
    for (int i = 0; i < 4; i++)
#pragma unroll
        for (int j = 0; j < 4; j++)
#pragma unroll
            for (int q = 0; q < 4; q++) acc[i][j][q] = 0.0f;

    // stage loader: 32 k-rows x 128 floats for A and B (8 x 16B per thread)
    auto load_stage = [&](int kt, int s) {
        float* dstA = sm + s * STAGE_F;
        float* dstB = dstA + TILE_F;
#pragma unroll
        for (int i = 0; i < 8; i++) {
            int u = tid + i * 256;           // 0..2047
            int k = (u & 1023) >> 5;         // 0..31
            int c = u & 31;                  // 16B column
            if (u < 1024)
                cp16(smem_u32(dstA + k * PADW + c * 4),
                     A + (size_t)(kt * 32 + k) * NN + m0 + c * 4);
            else
                cp16(smem_u32(dstB + k * PADW + c * 4),
                     Bt + (size_t)(kt * 32 + k) * NN + n0 + c * 4);
        }
        CP_COMMIT();
    };

    load_stage(0, 0);

    for (int kt = 0; kt < 16; kt++) {
        if (kt + 1 < 16) {
            load_stage(kt + 1, (kt + 1) & 1);
            asm volatile("cp.async.wait_group 1;" ::: "memory");
        } else {
            asm volatile("cp.async.wait_group 0;" ::: "memory");
        }
        __syncthreads();

        const float* As = sm + (kt & 1) * STAGE_F;
        const float* Bs = As + TILE_F;

#pragma unroll
        for (int kk = 0; kk < 4; kk++) {
            const int kb = kk * 8 + (lane & 3);
            uint32_t a1[4][4], a2[4][4], b1[4][2], b2[4][2];
#pragma unroll
            for (int mt = 0; mt < 4; mt++) {
                int m = wm * 64 + mt * 16 + (lane >> 2);
                float v0 = As[kb * PADW + m];
                float v1 = As[kb * PADW + m + 8];
                float v2 = As[(kb + 4) * PADW + m];
                float v3 = As[(kb + 4) * PADW + m + 8];
                split_tf32(v0, a1[mt][0], a2[mt][0]);
                split_tf32(v1, a1[mt][1], a2[mt][1]);
                split_tf32(v2, a1[mt][2], a2[mt][2]);
                split_tf32(v3, a1[mt][3], a2[mt][3]);
            }
#pragma unroll
            for (int nt = 0; nt < 4; nt++) {
                int n = wn * 32 + nt * 8 + (lane >> 2);
                float v0 = Bs[kb * PADW + n];
                float v1 = Bs[(kb + 4) * PADW + n];
                split_tf32(v0, b1[nt][0], b2[nt][0]);
                split_tf32(v1, b1[nt][1], b2[nt][1]);
            }
#pragma unroll
            for (int mt = 0; mt < 4; mt++)
#pragma unroll
                for (int nt = 0; nt < 4; nt++) {
                    MMA8(acc[mt][nt], a1[mt], b1[nt]);
                    MMA8(acc[mt][nt], a1[mt], b2[nt]);
                    MMA8(acc[mt][nt], a2[mt], b1[nt]);
                }
        }
        __syncthreads();
    }

    // epilogue
    const float scl = 0.04419417382415922f;   // 1/sqrt(512)
    float* C = g_logits + (size_t)b * NN * NN;
#pragma unroll
    for (int mt = 0; mt < 4; mt++) {
        int row = m0 + wm * 64 + mt * 16 + (lane >> 2);
#pragma unroll
        for (int nt = 0; nt < 4; nt++) {
            int col = n0 + wn * 32 + nt * 8 + 2 * (lane & 3);
            float2 lo = make_float2(acc[mt][nt][0] * scl, acc[mt][nt][1] * scl);
            float2 hi = make_float2(acc[mt][nt][2] * scl, acc[mt][nt][3] * scl);
            *(float2*)(C + (size_t)row * NN + col) = lo;
            *(float2*)(C + (size_t)(row + 8) * NN + col) = hi;
        }
    }
}

// ---------------------------------------------------------------------------
// Softmax + colsum + per-row top-16 (unchanged from passing R2 kernel)
// ---------------------------------------------------------------------------
__global__ __launch_bounds__(256) void k_softmax_top() {
    const int b = blockIdx.y;
    const int row0 = blockIdx.x * 32;
    const int tid = threadIdx.x;
    const int lane = tid & 31;
    const int wid = tid >> 5;

    __shared__ float colAcc[NN];
    __shared__ float s_red[8];
    __shared__ u64 s_k[8];

    for (int i = tid; i < NN; i += 256) colAcc[i] = 0.0f;
    __syncthreads();

    for (int r = 0; r < 32; r++) {
        const int row = row0 + r;
        const float* L = g_logits + ((size_t)b * NN + row) * NN;
        float v[8];
#pragma unroll
        for (int k = 0; k < 8; k++) v[k] = L[tid + k * 256];

        float m = v[0];
#pragma unroll
        for (int k = 1; k < 8; k++) m = fmaxf(m, v[k]);
#pragma unroll
        for (int off = 16; off; off >>= 1)
            m = fmaxf(m, __shfl_xor_sync(0xFFFFFFFFu, m, off));
        if (lane == 0) s_red[wid] = m;
        __syncthreads();
        float bm = s_red[0];
#pragma unroll
        for (int w = 1; w < 8; w++) bm = fmaxf(bm, s_red[w]);
        __syncthreads();

        float sum = 0.0f;
#pragma unroll
        for (int k = 0; k < 8; k++) { v[k] = fast_exp(v[k] - bm); sum += v[k]; }
#pragma unroll
        for (int off = 16; off; off >>= 1)
            sum += __shfl_xor_sync(0xFFFFFFFFu, sum, off);
        if (lane == 0) s_red[wid] = sum;
        __syncthreads();
        float Z = 0.0f;
#pragma unroll
        for (int w = 0; w < 8; w++) Z += s_red[w];
        float inv = 1.0f / Z;
#pragma unroll
        for (int k = 0; k < 8; k++) { v[k] *= inv; colAcc[tid + k * 256] += v[k]; }

        unsigned msk = 0;
        for (int it = 0; it < TOPK; it++) {
            u64 best = 0ull;
#pragma unroll
            for (int k = 0; k < 8; k++) {
                if (msk & (1u << k)) continue;
                unsigned col = (unsigned)tid + (unsigned)k * 256u;
                u64 key = ((u64)__float_as_uint(v[k]) << 32) | (u64)(0xFFFFFFFFu - col);
                if (key > best) best = key;
            }
#pragma unroll
            for (int off = 16; off; off >>= 1) {
                u64 o = __shfl_xor_sync(0xFFFFFFFFu, best, off);
                if (o > best) best = o;
            }
            __syncthreads();
            if (lane == 0) s_k[wid] = best;
            __syncthreads();
            u64 g = s_k[0];
#pragma unroll
            for (int w = 1; w < 8; w++) if (s_k[w] > g) g = s_k[w];
            unsigned col = 0xFFFFFFFFu - (unsigned)(g & 0xFFFFFFFFu);
            if ((col & 255u) == (unsigned)tid) msk |= 1u << (col >> 8);
            if (tid == 0) {
                g_topval[((size_t)b * NN + row) * TOPK + it] = __uint_as_float((unsigned)(g >> 32));
                g_topcol[((size_t)b * NN + row) * TOPK + it] = (int)col;
            }
        }
        __syncthreads();
    }

    for (int i = tid; i < NN; i += 256)
        atomicAdd(&g_colsum[b * NN + i], colAcc[i]);
}

// ---------------------------------------------------------------------------
// Tail: smem-cached greedy matching + Kabsch (fp64 Jacobi) + translation
// ---------------------------------------------------------------------------
__global__ __launch_bounds__(256) void k_match_tail(const float* __restrict__ src,
                                                    const float* __restrict__ tgt,
                                                    float* __restrict__ out) {
    const int b = blockIdx.x;
    const int tid = threadIdx.x;
    const int lane = tid & 31;
    const int wid = tid >> 5;

    __shared__ u64 curk[NN];                 // 16 KB
    __shared__ unsigned short ptrs[NN];
    __shared__ unsigned char usedc[NN];
    __shared__ u64 wred[8];
    __shared__ float sredf[8];
    __shared__ float sums[6];
    __shared__ int selR[NSAMP], selC[NSAMP];

    float a[6] = {0, 0, 0, 0, 0, 0};
    for (int n = tid; n < NN; n += 256) {
        const float* sp = src + ((size_t)b * NN + n) * 3;
        a[0] += sp[0]; a[1] += sp[1]; a[2] += sp[2];
        float w = g_colsum[b * NN + n];
        const float* tp = tgt + ((size_t)b * NN + n) * 3;
        a[3] += tp[0] * w; a[4] += tp[1] * w; a[5] += tp[2] * w;
    }
#pragma unroll
    for (int q = 0; q < 6; q++) {
        float v = a[q];
#pragma unroll
        for (int off = 16; off; off >>= 1) v += __shfl_xor_sync(0xFFFFFFFFu, v, off);
        if (lane == 0) sredf[wid] = v;
        __syncthreads();
        if (tid == 0) {
            float s = 0;
#pragma unroll
            for (int w = 0; w < 8; w++) s += sredf[w];
            sums[q] = s;
        }
        __syncthreads();
    }

    for (int r = tid; r < NN; r += 256) {
        usedc[r] = 0;
        ptrs[r] = 0;
        float v = g_topval[((size_t)b * NN + r) * TOPK];
        int c = g_topcol[((size_t)b * NN + r) * TOPK];
        curk[r] = ((u64)__float_as_uint(v) << 32) | ((u64)(2047 - r) << 11) | (u64)c;
    }
    __syncthreads();

    for (int it = 0; it < NSAMP; it++) {
        u64 best = 0ull;
#pragma unroll
        for (int k = 0; k < 8; k++) {
            u64 x = curk[tid + k * 256];
            if (x > best) best = x;
        }
#pragma unroll
        for (int off = 16; off; off >>= 1) {
            u64 o = __shfl_xor_sync(0xFFFFFFFFu, best, off);
            if (o > best) best = o;
        }
        if (lane == 0) wred[wid] = best;
        __syncthreads();
        if (tid == 0) {
            u64 g = wred[0];
#pragma unroll
            for (int w = 1; w < 8; w++) if (wred[w] > g) g = wred[w];
            int r = 2047 - (int)((g >> 11) & 0x7FF);
            int c = (int)(g & 0x7FF);
            selR[it] = r; selC[it] = c;
            usedc[c] = 1;
            curk[r] = 0ull;
        }
        __syncthreads();
        int cstar = selC[it];
#pragma unroll
        for (int k = 0; k < 8; k++) {
            int r = tid + k * 256;
            u64 x = curk[r];
            if (x && (int)(x & 0x7FF) == cstar) {
                const int* tc = &g_topcol[((size_t)b * NN + r) * TOPK];
                const float* tv = &g_topval[((size_t)b * NN + r) * TOPK];
                int p = ptrs[r];
                do { p++; } while (usedc[tc[p]]);
                ptrs[r] = (unsigned short)p;
                curk[r] = ((u64)__float_as_uint(tv[p]) << 32) |
                          ((u64)(2047 - r) << 11) | (u64)tc[p];
            }
        }
        __syncthreads();
    }

    if (tid != 0) return;

    // ---- Kabsch (fp64 Jacobi) ----
    double sp[NSAMP][3], tp[NSAMP][3];
    double ms[3] = {0, 0, 0}, mt[3] = {0, 0, 0};
    for (int s = 0; s < NSAMP; s++) {
        const float* ps = src + ((size_t)b * NN + selR[s]) * 3;
        const float* pt = tgt + ((size_t)b * NN + selC[s]) * 3;
        for (int i = 0; i < 3; i++) {
            sp[s][i] = (double)ps[i]; ms[i] += sp[s][i];
            tp[s][i] = (double)pt[i]; mt[i] += tp[s][i];
        }
    }
    for (int i = 0; i < 3; i++) { ms[i] /= NSAMP; mt[i] /= NSAMP; }

    double Hm[3][3] = {{0,0,0},{0,0,0},{0,0,0}};
    for (int s = 0; s < NSAMP; s++)
        for (int i = 0; i < 3; i++)
            for (int j = 0; j < 3; j++)
                Hm[i][j] += (sp[s][i] - ms[i]) * (tp[s][j] - mt[j]);

    double Aq[3][3];
    for (int i = 0; i < 3; i++)
        for (int j = 0; j < 3; j++) {
            double acc = 0;
            for (int k = 0; k < 3; k++) acc += Hm[k][i] * Hm[k][j];
            Aq[i][j] = acc;
        }
    double Vv[3][3] = {{1,0,0},{0,1,0},{0,0,1}};
    const int prs[3][2] = {{0,1},{0,2},{1,2}};
    for (int rot = 0; rot < 24; rot++) {
        int p = prs[rot % 3][0], q = prs[rot % 3][1];
        double apq = Aq[p][q];
        if (fabs(apq) < 1e-300) continue;
        double theta = (Aq[q][q] - Aq[p][p]) / (2.0 * apq);
        double tt = (theta >= 0 ? 1.0 : -1.0) / (fabs(theta) + sqrt(theta * theta + 1.0));
        double c = 1.0 / sqrt(tt * tt + 1.0);
        double s = tt * c;
        for (int k = 0; k < 3; k++) {
            double akp = Aq[k][p], akq = Aq[k][q];
            Aq[k][p] = c * akp - s * akq;
            Aq[k][q] = s * akp + c * akq;
        }
        for (int k = 0; k < 3; k++) {
            double apk = Aq[p][k], aqk = Aq[q][k];
            Aq[p][k] = c * apk - s * aqk;
            Aq[q][k] = s * apk + c * aqk;
        }
        for (int k = 0; k < 3; k++) {
            double vkp = Vv[k][p], vkq = Vv[k][q];
            Vv[k][p] = c * vkp - s * vkq;
            Vv[k][q] = s * vkp + c * vkq;
        }
    }
    double lam[3] = {Aq[0][0], Aq[1][1], Aq[2][2]};
    int ord[3] = {0, 1, 2};
    for (int i = 0; i < 2; i++)
        for (int j = i + 1; j < 3; j++)
            if (lam[ord[j]] > lam[ord[i]]) { int t0 = ord[i]; ord[i] = ord[j]; ord[j] = t0; }

    double Vs[3][3], U[3][3];
    for (int i = 0; i < 3; i++) {
        double sg = sqrt(fmax(lam[ord[i]], 1e-300));
        for (int k = 0; k < 3; k++) Vs[k][i] = Vv[k][ord[i]];
        for (int k = 0; k < 3; k++) {
            double acc = 0;
            for (int j = 0; j < 3; j++) acc += Hm[k][j] * Vs[j][i];
            U[k][i] = acc / sg;
        }
    }
    double Rr[3][3];
    for (int i = 0; i < 3; i++)
        for (int j = 0; j < 3; j++) {
            double acc = 0;
            for (int k = 0; k < 3; k++) acc += Vs[i][k] * U[j][k];
            Rr[i][j] = acc;
        }
    double det = Rr[0][0] * (Rr[1][1] * Rr[2][2] - Rr[1][2] * Rr[2][1])
               - Rr[0][1] * (Rr[1][0] * Rr[2][2] - Rr[1][2] * Rr[2][0])
               + Rr[0][2] * (Rr[1][0] * Rr[2][1] - Rr[1][1] * Rr[2][0]);
    if (det < 0) {
        for (int k = 0; k < 3; k++) Vs[k][2] = -Vs[k][2];
        for (int i = 0; i < 3; i++)
            for (int j = 0; j < 3; j++) {
                double acc = 0;
                for (int k = 0; k < 3; k++) acc += Vs[i][k] * U[j][k];
                Rr[i][j] = acc;
            }
    }

    double msrc[3] = {sums[0] / (double)NN, sums[1] / (double)NN, sums[2] / (double)NN};
    double corr[3] = {sums[3] / (double)NN, sums[4] / (double)NN, sums[5] / (double)NN};
    for (int i = 0; i < 3; i++)
        for (int j = 0; j < 3; j++)
            out[b * 9 + i * 3 + j] = (float)Rr[i][j];
    for (int i = 0; i < 3; i++) {
        double ti = -(Rr[i][0] * msrc[0] + Rr[i][1] * msrc[1] + Rr[i][2] * msrc[2]) + corr[i];
        out[BB * 9 + b * 3 + i] = (float)ti;
    }
}

// ---------------------------------------------------------------------------
extern "C" void kernel_launch(void* const* d_in, const int* in_sizes, int n_in,
                              void* d_out, int out_size) {
    const float* se  = (const float*)d_in[0];
    const float* te  = (const float*)d_in[1];
    const float* src = (const float*)d_in[2];
    const float* tgt = (const float*)d_in[3];
    float* out = (float*)d_out;

    const int smem_bytes = 2 * STAGE_F * (int)sizeof(float);   // 67584
    cudaFuncSetAttribute(k_gemm_mma, cudaFuncAttributeMaxDynamicSharedMemorySize,
                         smem_bytes);

    k_zero_colsum<<<(BB * NN + 255) / 256, 256>>>();
    k_gemm_mma<<<dim3(16, 16, BB), 256, smem_bytes>>>(se, te);
    k_softmax_top<<<dim3(NN / 32, BB), 256>>>();
    k_match_tail<<<BB, 256>>>(src, tgt, out);
}